// round 1
// baseline (speedup 1.0000x reference)
#include <cuda_runtime.h>
#include <cstdint>
#include <math.h>

#define NROW   100000
#define FD     128
#define BATCH  64
#define KP1    16385
#define NELEM  (BATCH*KP1)        // 1048640
#define INV_T  (1.0f/0.07f)
#define EPSC   1e-7f
#define MPN    0.16384f           // 16384/100000
#define CCONST (MPN + EPSC)
#define NBX    9                  // gather/loss blocks per batch row
#define NPART  (BATCH*NBX)        // 576

// ---------------- scratch (device globals; no allocation) ----------------
__device__ float g_y [2*BATCH*FD];        // embed pre-norm
__device__ float g_vT[2*FD*BATCH];        // normalized, transposed [side][d][b]
__device__ float g_S [2][6400000];        // [side][row*64+b] similarity table (51.2MB)
__device__ float g_e [2][NELEM];          // gathered exp values
__device__ float g_pZ[2][NPART];          // Z partial sums
__device__ float g_pL[2][NPART];          // loss partial sums

// ---------------- f32x2 packed FMA helpers ----------------
__device__ __forceinline__ unsigned long long pk2(float x, float y) {
    unsigned long long r;
    asm("mov.b64 %0, {%1, %2};" : "=l"(r) : "f"(x), "f"(y));
    return r;
}
__device__ __forceinline__ unsigned long long fma2(unsigned long long a,
                                                   unsigned long long b,
                                                   unsigned long long c) {
    unsigned long long d;
    asm("fma.rn.f32x2 %0, %1, %2, %3;" : "=l"(d) : "l"(a), "l"(b), "l"(c));
    return d;
}

// fixed-order deterministic block reduction (256 threads)
__device__ __forceinline__ float block_reduce_256(float v) {
    __shared__ float sh[8];
    #pragma unroll
    for (int o = 16; o > 0; o >>= 1) v += __shfl_xor_sync(0xffffffffu, v, o);
    __syncthreads();
    if ((threadIdx.x & 31) == 0) sh[threadIdx.x >> 5] = v;
    __syncthreads();
    float t = 0.f;
    #pragma unroll
    for (int i = 0; i < 8; i++) t += sh[i];
    return t;
}

// ---------------- K1: embed GEMM  y = f @ W^T + bias ----------------
// grid (4 feature-tiles, 2 sides), block 256 = 32 feat x 8 batch-groups
__global__ void embed_kernel(const float* __restrict__ f_s, const float* __restrict__ f_t,
                             const float* __restrict__ Ws,  const float* __restrict__ bs,
                             const float* __restrict__ Wt,  const float* __restrict__ bt) {
    int side = blockIdx.y;
    const float* f    = side ? f_t : f_s;
    const float* W    = side ? Wt  : Ws;
    const float* bias = side ? bt  : bs;
    int dim = side ? 2048 : 1024;

    __shared__ float Fs[64][65];
    __shared__ float Wc[32][65];

    int tid = threadIdx.x;
    int tx  = tid & 31;      // feature within tile
    int bg  = tid >> 5;      // batch group (8 batches each)
    int ftb = blockIdx.x * 32;

    float acc[8] = {0.f,0.f,0.f,0.f,0.f,0.f,0.f,0.f};

    for (int k0 = 0; k0 < dim; k0 += 64) {
        for (int i = tid; i < 64*64; i += 256) {
            int bb = i >> 6, kk = i & 63;
            Fs[bb][kk] = f[bb*dim + k0 + kk];
        }
        for (int i = tid; i < 32*64; i += 256) {
            int r = i >> 6, kk = i & 63;
            Wc[r][kk] = W[(ftb + r)*dim + k0 + kk];
        }
        __syncthreads();
        #pragma unroll 8
        for (int kk = 0; kk < 64; kk++) {
            float w = Wc[tx][kk];
            #pragma unroll
            for (int j = 0; j < 8; j++) acc[j] += Fs[bg*8 + j][kk] * w;
        }
        __syncthreads();
    }
    float bv = bias[ftb + tx];
    #pragma unroll
    for (int j = 0; j < 8; j++)
        g_y[side*BATCH*FD + (bg*8 + j)*FD + ftb + tx] = acc[j] + bv;
}

// ---------------- K2: l2norm + transpose ----------------
// grid (64 batches, 2 sides), block 128 (= feature dim)
__global__ void norm_kernel() {
    int side = blockIdx.y, b = blockIdx.x, d = threadIdx.x;
    float v = g_y[side*BATCH*FD + b*FD + d];
    float s = v * v;
    #pragma unroll
    for (int o = 16; o > 0; o >>= 1) s += __shfl_xor_sync(0xffffffffu, s, o);
    __shared__ float sh[4];
    if ((d & 31) == 0) sh[d >> 5] = s;
    __syncthreads();
    float tot = sh[0] + sh[1] + sh[2] + sh[3];
    float inv = 1.0f / sqrtf(tot);
    g_vT[side*FD*BATCH + d*BATCH + b] = v * inv;   // [side][d][b]
}

// ---------------- K3: main GEMM  S[r][b] = dot(memory[r], v[b]) ----------------
// side 0: memory_v2 x v_s   side 1: memory_v1 x v_t
// grid (782, 2), block 256. Per thread: 4 rows x 8 cols (4 float2 accs) via FFMA2.
__global__ void gemm_kernel(const float* __restrict__ mem1, const float* __restrict__ mem2) {
    int side = blockIdx.y;
    const float* memb = side ? mem1 : mem2;

    __shared__ float vsm[FD*BATCH];  // [d][b], 32KB
    int tid = threadIdx.x;
    for (int i = tid; i < FD*BATCH; i += 256)
        vsm[i] = g_vT[side*FD*BATCH + i];
    __syncthreads();

    int cg = tid & 7;        // col group: cols cg*8 .. cg*8+7
    int rg = tid >> 3;       // row group: 4 rows
    int r0 = blockIdx.x * 128 + rg * 4;

    const float4* rp[4];
    #pragma unroll
    for (int i = 0; i < 4; i++) {
        int r = r0 + i;
        int rc = (r < NROW) ? r : (NROW - 1);
        rp[i] = reinterpret_cast<const float4*>(memb + (size_t)rc * FD);
    }

    unsigned long long acc[4][4];
    #pragma unroll
    for (int i = 0; i < 4; i++)
        #pragma unroll
        for (int c = 0; c < 4; c++) acc[i][c] = 0ull;

    const unsigned long long* vsmu = reinterpret_cast<const unsigned long long*>(vsm);
    int cb = cg * 4;         // float2 column base

    #pragma unroll 2
    for (int j = 0; j < 32; j++) {           // 4 d's per iter
        float4 mf[4];
        #pragma unroll
        for (int i = 0; i < 4; i++) mf[i] = rp[i][j];
        #pragma unroll
        for (int jj = 0; jj < 4; jj++) {
            int d = 4*j + jj;
            unsigned long long bv0 = vsmu[d*32 + cb + 0];
            unsigned long long bv1 = vsmu[d*32 + cb + 1];
            unsigned long long bv2 = vsmu[d*32 + cb + 2];
            unsigned long long bv3 = vsmu[d*32 + cb + 3];
            #pragma unroll
            for (int i = 0; i < 4; i++) {
                float a = reinterpret_cast<const float*>(&mf[i])[jj];
                unsigned long long aa = pk2(a, a);
                acc[i][0] = fma2(aa, bv0, acc[i][0]);
                acc[i][1] = fma2(aa, bv1, acc[i][1]);
                acc[i][2] = fma2(aa, bv2, acc[i][2]);
                acc[i][3] = fma2(aa, bv3, acc[i][3]);
            }
        }
    }

    float* Sout = g_S[side];
    #pragma unroll
    for (int i = 0; i < 4; i++) {
        int r = r0 + i;
        if (r < NROW) {
            float2* so = reinterpret_cast<float2*>(Sout + (size_t)r * BATCH + cg * 8);
            #pragma unroll
            for (int c = 0; c < 4; c++)
                so[c] = *reinterpret_cast<float2*>(&acc[i][c]);
        }
    }
}

// ---------------- K4: gather + exp + Z partials ----------------
// grid (9, 64, 2), block 256, 8 elems/thread
__global__ void gather_kernel(const int* __restrict__ idx, const int* __restrict__ cidx) {
    int side = blockIdx.z, b = blockIdx.y, bx = blockIdx.x;
    int t = threadIdx.x;
    const float* Sv = g_S[side];
    float* ev = g_e[side];
    float sum = 0.f;
    #pragma unroll
    for (int i = 0; i < 8; i++) {
        int k = bx*2048 + i*256 + t;
        if (k < KP1) {
            int row = (k == 0) ? idx[b] : cidx[b*KP1 + k];
            float s = Sv[(size_t)row * BATCH + b];
            float e = expf(s * INV_T);
            ev[b*KP1 + k] = e;
            sum += e;
        }
    }
    float tot = block_reduce_256(sum);
    if (t == 0) g_pZ[side][b*NBX + bx] = tot;
}

// ---------------- K5: loss partials ----------------
// grid (9, 64, 2), block 256. Each block reduces Z partials itself (deterministic).
__global__ void loss_kernel() {
    int side = blockIdx.z, b = blockIdx.y, bx = blockIdx.x;
    int t = threadIdx.x;

    float zs = 0.f;
    for (int i = t; i < NPART; i += 256) zs += g_pZ[side][i];
    float ztot = block_reduce_256(zs);
    float Z = (ztot / (float)NELEM) * (float)NROW;   // mean * n_data
    float invZ = 1.0f / Z;

    const float* ev = g_e[side];
    float acc = 0.f;
    #pragma unroll
    for (int i = 0; i < 8; i++) {
        int k = bx*2048 + i*256 + t;
        if (k < KP1) {
            float x = ev[b*KP1 + k] * invZ;
            // -(log_D1) = log1p(c/x0) ; -(log_D0) = log1p((x+EPS)/mPn)
            acc += (k == 0) ? log1pf(CCONST / x) : log1pf((x + EPSC) / MPN);
        }
    }
    float tot = block_reduce_256(acc);
    if (t == 0) g_pL[side][b*NBX + bx] = tot;
}

// ---------------- K6: final scalar ----------------
__global__ void final_kernel(float* __restrict__ out) {
    int t = threadIdx.x;
    const float* p = &g_pL[0][0];
    float s = 0.f;
    for (int i = t; i < 2*NPART; i += 256) s += p[i];
    float tot = block_reduce_256(s);
    if (t == 0) out[0] = tot / (float)BATCH;
}

// ---------------- launch ----------------
extern "C" void kernel_launch(void* const* d_in, const int* in_sizes, int n_in,
                              void* d_out, int out_size) {
    const float* f_s  = (const float*)d_in[0];
    const float* f_t  = (const float*)d_in[1];
    const int*   idx  = (const int*)  d_in[2];
    const int*   cidx = (const int*)  d_in[3];
    const float* Ws   = (const float*)d_in[4];
    const float* bs   = (const float*)d_in[5];
    const float* Wt   = (const float*)d_in[6];
    const float* bt   = (const float*)d_in[7];
    const float* mem1 = (const float*)d_in[8];   // memory_v1 (v_t side)
    const float* mem2 = (const float*)d_in[9];   // memory_v2 (v_s side)

    embed_kernel <<<dim3(4, 2),        256>>>(f_s, f_t, Ws, bs, Wt, bt);
    norm_kernel  <<<dim3(BATCH, 2),    128>>>();
    gemm_kernel  <<<dim3(782, 2),      256>>>(mem1, mem2);
    gather_kernel<<<dim3(NBX, BATCH, 2), 256>>>(idx, cidx);
    loss_kernel  <<<dim3(NBX, BATCH, 2), 256>>>();
    final_kernel <<<1,                 256>>>((float*)d_out);
}

// round 2
// speedup vs baseline: 1.0989x; 1.0989x over previous
#include <cuda_runtime.h>
#include <cstdint>
#include <math.h>

#define NROW   100000
#define FD     128
#define BATCH  64
#define KP1    16385
#define NELEM  (BATCH*KP1)        // 1048640
#define INV_T  (1.0f/0.07f)
#define EPSC   1e-7f
#define MPN    0.16384f           // 16384/100000
#define CCONST (MPN + EPSC)
#define NBX    9                  // gather/loss blocks per batch row
#define NPART  (BATCH*NBX)        // 576

#define AP     132                // padded A row (floats), %4==0 for float4
#define GEMM_SMEM ((128*AP + FD*BATCH) * 4)   // 67584 + 32768 = 100352 B

// ---------------- scratch (device globals; no allocation) ----------------
__device__ float g_y [2*BATCH*FD];        // embed pre-norm
__device__ float g_vT[2*FD*BATCH];        // normalized, transposed [side][d][b]
__device__ float g_S [2][6400000];        // [side][row*64+b] similarity (51.2MB)
__device__ float g_e [2][NELEM];          // gathered exp values
__device__ float g_pZ[2][NPART];          // Z partial sums
__device__ float g_pL[NPART];             // loss partials (both sides folded)

// ---------------- f32x2 packed FMA helpers ----------------
__device__ __forceinline__ unsigned long long pk2(float x, float y) {
    unsigned long long r;
    asm("mov.b64 %0, {%1, %2};" : "=l"(r) : "f"(x), "f"(y));
    return r;
}
__device__ __forceinline__ unsigned long long fma2(unsigned long long a,
                                                   unsigned long long b,
                                                   unsigned long long c) {
    unsigned long long d;
    asm("fma.rn.f32x2 %0, %1, %2, %3;" : "=l"(d) : "l"(a), "l"(b), "l"(c));
    return d;
}

// fixed-order deterministic block reduction (256 threads)
__device__ __forceinline__ float block_reduce_256(float v) {
    __shared__ float sh[8];
    #pragma unroll
    for (int o = 16; o > 0; o >>= 1) v += __shfl_xor_sync(0xffffffffu, v, o);
    __syncthreads();
    if ((threadIdx.x & 31) == 0) sh[threadIdx.x >> 5] = v;
    __syncthreads();
    float t = 0.f;
    #pragma unroll
    for (int i = 0; i < 8; i++) t += sh[i];
    return t;
}

// ---------------- K1: embed GEMM  y = f @ W^T + bias ----------------
__global__ void embed_kernel(const float* __restrict__ f_s, const float* __restrict__ f_t,
                             const float* __restrict__ Ws,  const float* __restrict__ bs,
                             const float* __restrict__ Wt,  const float* __restrict__ bt) {
    int side = blockIdx.y;
    const float* f    = side ? f_t : f_s;
    const float* W    = side ? Wt  : Ws;
    const float* bias = side ? bt  : bs;
    int dim = side ? 2048 : 1024;

    __shared__ float Fs[64][65];
    __shared__ float Wc[32][65];

    int tid = threadIdx.x;
    int tx  = tid & 31;      // feature within tile
    int bg  = tid >> 5;      // batch group (8 batches each)
    int ftb = blockIdx.x * 32;

    float acc[8] = {0.f,0.f,0.f,0.f,0.f,0.f,0.f,0.f};

    for (int k0 = 0; k0 < dim; k0 += 64) {
        for (int i = tid; i < 64*64; i += 256) {
            int bb = i >> 6, kk = i & 63;
            Fs[bb][kk] = f[bb*dim + k0 + kk];
        }
        for (int i = tid; i < 32*64; i += 256) {
            int r = i >> 6, kk = i & 63;
            Wc[r][kk] = W[(ftb + r)*dim + k0 + kk];
        }
        __syncthreads();
        #pragma unroll 8
        for (int kk = 0; kk < 64; kk++) {
            float w = Wc[tx][kk];
            #pragma unroll
            for (int j = 0; j < 8; j++) acc[j] += Fs[bg*8 + j][kk] * w;
        }
        __syncthreads();
    }
    float bv = bias[ftb + tx];
    #pragma unroll
    for (int j = 0; j < 8; j++)
        g_y[side*BATCH*FD + (bg*8 + j)*FD + ftb + tx] = acc[j] + bv;
}

// ---------------- K2: l2norm + transpose ----------------
__global__ void norm_kernel() {
    int side = blockIdx.y, b = blockIdx.x, d = threadIdx.x;
    float v = g_y[side*BATCH*FD + b*FD + d];
    float s = v * v;
    #pragma unroll
    for (int o = 16; o > 0; o >>= 1) s += __shfl_xor_sync(0xffffffffu, s, o);
    __shared__ float sh[4];
    if ((d & 31) == 0) sh[d >> 5] = s;
    __syncthreads();
    float tot = sh[0] + sh[1] + sh[2] + sh[3];
    float inv = 1.0f / sqrtf(tot);
    g_vT[side*FD*BATCH + d*BATCH + b] = v * inv;   // [side][d][b]
}

// ---------------- K3: main GEMM  S[r][b] = dot(memory[r], v[b]) ----------------
// smem-tiled: block = 128 rows x 64 cols, K=128. Coalesced global loads into
// padded smem, then per-thread 4 rows x 8 cols with fma.rn.f32x2.
__global__ void __launch_bounds__(256, 2)
gemm_kernel(const float* __restrict__ mem1, const float* __restrict__ mem2) {
    int side = blockIdx.y;
    const float* memb = side ? mem1 : mem2;

    extern __shared__ float sm[];
    float* As = sm;                 // [128][AP]
    float* vs = sm + 128*AP;        // [d][b] = [128][64]

    int tid = threadIdx.x;
    int r0blk = blockIdx.x * 128;

    // load v tile (L2-resident, tiny)
    #pragma unroll
    for (int i = 0; i < (FD*BATCH)/256; i++)
        vs[tid + i*256] = g_vT[side*FD*BATCH + tid + i*256];

    // load A tile coalesced: 128 rows x 32 float4
    {
        float4* As4 = reinterpret_cast<float4*>(As);
        const float4* gm = reinterpret_cast<const float4*>(memb);
        #pragma unroll
        for (int j = 0; j < 16; j++) {
            int lin = tid + j*256;           // float4 index within tile
            int r  = lin >> 5;               // 0..127
            int d4 = lin & 31;               // 0..31
            int gr = r0blk + r;
            if (gr >= NROW) gr = NROW - 1;
            As4[r*(AP/4) + d4] = gm[(size_t)gr*32 + d4];
        }
    }
    __syncthreads();

    int cg = tid & 7;                // col group -> cols cg*8 .. +7
    int rg = tid >> 3;               // row group -> rows rg*4 .. +3
    int c0 = cg * 8;
    int rbase = rg * 4;

    unsigned long long acc[4][4];
    #pragma unroll
    for (int i = 0; i < 4; i++)
        #pragma unroll
        for (int c = 0; c < 4; c++) acc[i][c] = 0ull;

    #pragma unroll 4
    for (int d = 0; d < FD; d += 4) {
        float4 a0 = *reinterpret_cast<const float4*>(&As[(rbase+0)*AP + d]);
        float4 a1 = *reinterpret_cast<const float4*>(&As[(rbase+1)*AP + d]);
        float4 a2 = *reinterpret_cast<const float4*>(&As[(rbase+2)*AP + d]);
        float4 a3 = *reinterpret_cast<const float4*>(&As[(rbase+3)*AP + d]);
        const float* ap0 = reinterpret_cast<const float*>(&a0);
        const float* ap1 = reinterpret_cast<const float*>(&a1);
        const float* ap2 = reinterpret_cast<const float*>(&a2);
        const float* ap3 = reinterpret_cast<const float*>(&a3);
        #pragma unroll
        for (int jj = 0; jj < 4; jj++) {
            ulonglong2 v01 = *reinterpret_cast<const ulonglong2*>(&vs[(d+jj)*BATCH + c0]);
            ulonglong2 v23 = *reinterpret_cast<const ulonglong2*>(&vs[(d+jj)*BATCH + c0 + 4]);
            unsigned long long aa;
            aa = pk2(ap0[jj], ap0[jj]);
            acc[0][0] = fma2(aa, v01.x, acc[0][0]);
            acc[0][1] = fma2(aa, v01.y, acc[0][1]);
            acc[0][2] = fma2(aa, v23.x, acc[0][2]);
            acc[0][3] = fma2(aa, v23.y, acc[0][3]);
            aa = pk2(ap1[jj], ap1[jj]);
            acc[1][0] = fma2(aa, v01.x, acc[1][0]);
            acc[1][1] = fma2(aa, v01.y, acc[1][1]);
            acc[1][2] = fma2(aa, v23.x, acc[1][2]);
            acc[1][3] = fma2(aa, v23.y, acc[1][3]);
            aa = pk2(ap2[jj], ap2[jj]);
            acc[2][0] = fma2(aa, v01.x, acc[2][0]);
            acc[2][1] = fma2(aa, v01.y, acc[2][1]);
            acc[2][2] = fma2(aa, v23.x, acc[2][2]);
            acc[2][3] = fma2(aa, v23.y, acc[2][3]);
            aa = pk2(ap3[jj], ap3[jj]);
            acc[3][0] = fma2(aa, v01.x, acc[3][0]);
            acc[3][1] = fma2(aa, v01.y, acc[3][1]);
            acc[3][2] = fma2(aa, v23.x, acc[3][2]);
            acc[3][3] = fma2(aa, v23.y, acc[3][3]);
        }
    }

    float* Sout = g_S[side];
    #pragma unroll
    for (int i = 0; i < 4; i++) {
        int r = r0blk + rbase + i;
        if (r < NROW) {
            float2 p0 = *reinterpret_cast<float2*>(&acc[i][0]);
            float2 p1 = *reinterpret_cast<float2*>(&acc[i][1]);
            float2 p2 = *reinterpret_cast<float2*>(&acc[i][2]);
            float2 p3 = *reinterpret_cast<float2*>(&acc[i][3]);
            float4 o0 = make_float4(p0.x, p0.y, p1.x, p1.y);
            float4 o1 = make_float4(p2.x, p2.y, p3.x, p3.y);
            *reinterpret_cast<float4*>(&Sout[(size_t)r*BATCH + c0])     = o0;
            *reinterpret_cast<float4*>(&Sout[(size_t)r*BATCH + c0 + 4]) = o1;
        }
    }
}

// ---------------- K4: gather + exp + Z partials (both sides fused) ----------------
// grid (NBX, 64), block 256, 8 k's x 2 sides per thread -> 16 independent loads
__global__ void gather_kernel(const int* __restrict__ idx, const int* __restrict__ cidx) {
    int b = blockIdx.y, bx = blockIdx.x;
    int t = threadIdx.x;
    const float* S0 = g_S[0];
    const float* S1 = g_S[1];
    float sum0 = 0.f, sum1 = 0.f;
    #pragma unroll
    for (int i = 0; i < 8; i++) {
        int k = bx*2048 + i*256 + t;
        if (k < KP1) {
            int row = (k == 0) ? idx[b] : cidx[b*KP1 + k];
            size_t off = (size_t)row * BATCH + b;
            float e0 = expf(S0[off] * INV_T);
            float e1 = expf(S1[off] * INV_T);
            g_e[0][b*KP1 + k] = e0;
            g_e[1][b*KP1 + k] = e1;
            sum0 += e0;
            sum1 += e1;
        }
    }
    float t0 = block_reduce_256(sum0);
    float t1 = block_reduce_256(sum1);
    if (t == 0) {
        g_pZ[0][b*NBX + bx] = t0;
        g_pZ[1][b*NBX + bx] = t1;
    }
}

// ---------------- K5: loss partials (both sides fused) ----------------
__global__ void loss_kernel() {
    int b = blockIdx.y, bx = blockIdx.x;
    int t = threadIdx.x;

    float z0 = 0.f, z1 = 0.f;
    for (int i = t; i < NPART; i += 256) { z0 += g_pZ[0][i]; z1 += g_pZ[1][i]; }
    float zt0 = block_reduce_256(z0);
    float zt1 = block_reduce_256(z1);
    float invZ0 = 1.0f / ((zt0 / (float)NELEM) * (float)NROW);
    float invZ1 = 1.0f / ((zt1 / (float)NELEM) * (float)NROW);

    float acc = 0.f;
    #pragma unroll
    for (int i = 0; i < 8; i++) {
        int k = bx*2048 + i*256 + t;
        if (k < KP1) {
            float x0 = g_e[0][b*KP1 + k] * invZ0;
            float x1 = g_e[1][b*KP1 + k] * invZ1;
            if (k == 0) {
                acc += log1pf(CCONST / x0) + log1pf(CCONST / x1);
            } else {
                acc += log1pf((x0 + EPSC) / MPN) + log1pf((x1 + EPSC) / MPN);
            }
        }
    }
    float tot = block_reduce_256(acc);
    if (t == 0) g_pL[b*NBX + bx] = tot;
}

// ---------------- K6: final scalar ----------------
__global__ void final_kernel(float* __restrict__ out) {
    int t = threadIdx.x;
    float s = 0.f;
    for (int i = t; i < NPART; i += 256) s += g_pL[i];
    float tot = block_reduce_256(s);
    if (t == 0) out[0] = tot / (float)BATCH;
}

// ---------------- launch ----------------
extern "C" void kernel_launch(void* const* d_in, const int* in_sizes, int n_in,
                              void* d_out, int out_size) {
    const float* f_s  = (const float*)d_in[0];
    const float* f_t  = (const float*)d_in[1];
    const int*   idx  = (const int*)  d_in[2];
    const int*   cidx = (const int*)  d_in[3];
    const float* Ws   = (const float*)d_in[4];
    const float* bs   = (const float*)d_in[5];
    const float* Wt   = (const float*)d_in[6];
    const float* bt   = (const float*)d_in[7];
    const float* mem1 = (const float*)d_in[8];   // memory_v1 (v_t side)
    const float* mem2 = (const float*)d_in[9];   // memory_v2 (v_s side)

    cudaFuncSetAttribute(gemm_kernel, cudaFuncAttributeMaxDynamicSharedMemorySize,
                         GEMM_SMEM);

    embed_kernel <<<dim3(4, 2),          256>>>(f_s, f_t, Ws, bs, Wt, bt);
    norm_kernel  <<<dim3(BATCH, 2),      128>>>();
    gemm_kernel  <<<dim3(782, 2),        256, GEMM_SMEM>>>(mem1, mem2);
    gather_kernel<<<dim3(NBX, BATCH),    256>>>(idx, cidx);
    loss_kernel  <<<dim3(NBX, BATCH),    256>>>();
    final_kernel <<<1,                   256>>>((float*)d_out);
}

// round 4
// speedup vs baseline: 2.7528x; 2.5051x over previous
#include <cuda_runtime.h>
#include <cuda_bf16.h>
#include <cstdint>
#include <math.h>

#define NROW   100000
#define FD     128
#define BATCH  64
#define KP1    16385
#define NELEM  (BATCH*KP1)        // 1048640
#define INV_T  (1.0f/0.07f)
#define EPSC   1e-7f
#define MPN    0.16384f           // 16384/100000
#define CCONST (MPN + EPSC)
#define NBX    9
#define NPART  (BATCH*NBX)        // 576

// ---- gemm smem layout (bf16 tiles, rows padded to 136 elems = 272B) ----
#define ROWB   272                 // bytes per padded row
#define OFF_AH 0                   // 128 x 272B = 34816
#define OFF_AL 34816
#define OFF_BH 69632               // 64 x 272B = 17408
#define OFF_BL 87040
#define SMEM_DYN 104448

// ---------------- scratch (device globals; no allocation) ----------------
__device__ float g_yp[4][2*BATCH*FD];                      // embed split-k partials
__device__ __align__(16) __nv_bfloat16 g_Bh[2][BATCH*FD];  // v hi, [side][b*128+d]
__device__ __align__(16) __nv_bfloat16 g_Bl[2][BATCH*FD];  // v lo
__device__ float g_S [2][6400000];                         // [side][row*64+b]
__device__ float g_e [2][NELEM];
__device__ float g_pZ[2][NPART];
__device__ float g_pL[NPART];
__device__ float g_pad;

// =================== portable PTX helpers (sm_80+ features) ===================
__device__ __forceinline__ uint32_t smem_u32(const void* p) {
    uint32_t a;
    asm("{ .reg .u64 t; cvta.to.shared.u64 t, %1; cvt.u32.u64 %0, t; }" : "=r"(a) : "l"(p));
    return a;
}
__device__ __forceinline__ void ldmx4(uint32_t* r, uint32_t addr) {
    asm volatile("ldmatrix.sync.aligned.m8n8.x4.shared.b16 {%0,%1,%2,%3}, [%4];"
                 : "=r"(r[0]), "=r"(r[1]), "=r"(r[2]), "=r"(r[3]) : "r"(addr));
}
__device__ __forceinline__ void mma16816(float* d, const uint32_t* a,
                                         uint32_t b0, uint32_t b1) {
    asm volatile(
        "mma.sync.aligned.m16n8k16.row.col.f32.bf16.bf16.f32 "
        "{%0,%1,%2,%3}, {%4,%5,%6,%7}, {%8,%9}, {%0,%1,%2,%3};"
        : "+f"(d[0]), "+f"(d[1]), "+f"(d[2]), "+f"(d[3])
        : "r"(a[0]), "r"(a[1]), "r"(a[2]), "r"(a[3]), "r"(b0), "r"(b1));
}

// ---------------- deterministic reductions ----------------
__device__ __forceinline__ float block_reduce_256(float v) {
    __shared__ float sh[8];
    #pragma unroll
    for (int o = 16; o > 0; o >>= 1) v += __shfl_xor_sync(0xffffffffu, v, o);
    __syncthreads();
    if ((threadIdx.x & 31) == 0) sh[threadIdx.x >> 5] = v;
    __syncthreads();
    float t = 0.f;
    #pragma unroll
    for (int i = 0; i < 8; i++) t += sh[i];
    return t;
}

// ---------------- K0: embed GEMM split-k  y_partial = f @ W^T ----------------
__global__ void embed_kernel(const float* __restrict__ f_s, const float* __restrict__ f_t,
                             const float* __restrict__ Ws,  const float* __restrict__ Wt) {
    int side = blockIdx.y;
    int ft = blockIdx.x & 3;
    int kc = blockIdx.x >> 2;
    const float* f = side ? f_t : f_s;
    const float* W = side ? Wt  : Ws;
    int dim  = side ? 2048 : 1024;
    int klen = dim >> 2;
    int kbeg = kc * klen;

    __shared__ float Fs[64][65];
    __shared__ float Wc[32][65];

    int tid = threadIdx.x;
    int tx  = tid & 31;
    int bg  = tid >> 5;
    int ftb = ft * 32;

    float acc[8] = {0.f,0.f,0.f,0.f,0.f,0.f,0.f,0.f};

    for (int k0 = kbeg; k0 < kbeg + klen; k0 += 64) {
        for (int i = tid; i < 64*64; i += 256) {
            int bb = i >> 6, kk = i & 63;
            Fs[bb][kk] = f[bb*dim + k0 + kk];
        }
        for (int i = tid; i < 32*64; i += 256) {
            int r = i >> 6, kk = i & 63;
            Wc[r][kk] = W[(ftb + r)*dim + k0 + kk];
        }
        __syncthreads();
        #pragma unroll 8
        for (int kk = 0; kk < 64; kk++) {
            float w = Wc[tx][kk];
            #pragma unroll
            for (int j = 0; j < 8; j++) acc[j] += Fs[bg*8 + j][kk] * w;
        }
        __syncthreads();
    }
    #pragma unroll
    for (int j = 0; j < 8; j++)
        g_yp[kc][side*BATCH*FD + (bg*8 + j)*FD + ftb + tx] = acc[j];
}

// ---------------- K1: sum partials + bias + l2norm + bf16 hi/lo B ----------------
__global__ void norm_kernel(const float* __restrict__ bs, const float* __restrict__ bt) {
    int side = blockIdx.y, b = blockIdx.x, d = threadIdx.x;
    const float* bias = side ? bt : bs;
    int o = side*BATCH*FD + b*FD + d;
    float y = g_yp[0][o] + g_yp[1][o] + g_yp[2][o] + g_yp[3][o] + bias[d];
    float s = y * y;
    #pragma unroll
    for (int of = 16; of > 0; of >>= 1) s += __shfl_xor_sync(0xffffffffu, s, of);
    __shared__ float sh[4];
    if ((d & 31) == 0) sh[d >> 5] = s;
    __syncthreads();
    float inv = rsqrtf(sh[0] + sh[1] + sh[2] + sh[3]);
    float v = y * inv;

    __nv_bfloat16 hi = __float2bfloat16_rn(v);
    __nv_bfloat16 lo = __float2bfloat16_rn(v - __bfloat162float(hi));
    g_Bh[side][b*FD + d] = hi;
    g_Bl[side][b*FD + d] = lo;
}

// ---------------- K2: trivial (keeps gemm at launch index 4) ----------------
__global__ void prep_kernel() {
    if (threadIdx.x == 0 && blockIdx.x == 0) g_pad = 0.f;
}

// ---------------- K3: tensor GEMM (mma.sync bf16-split, 3 terms) ----------------
// S[r][b] = dot(memory[r], v[b]); per CTA 128 rows x 64 cols x K=128.
__global__ void __launch_bounds__(256, 2)
gemm_mma(const float* __restrict__ mem1, const float* __restrict__ mem2) {
    int side = blockIdx.y;
    const float* A = side ? mem1 : mem2;
    int r0 = blockIdx.x * 128;

    extern __shared__ __align__(16) unsigned char sm[];
    uint32_t base_u = smem_u32(sm);

    int tid  = threadIdx.x;
    int lane = tid & 31;
    int warp = tid >> 5;

    // ---- B tiles: copy pre-split hi/lo [64][128] into padded smem ----
    {
        const uint2* sh = reinterpret_cast<const uint2*>(&g_Bh[side][0]);
        const uint2* sl = reinterpret_cast<const uint2*>(&g_Bl[side][0]);
        #pragma unroll
        for (int i = 0; i < 8; i++) {
            int idx = tid + i*256;            // 2048 uint2 per tile
            int r = idx >> 5, c = idx & 31;   // 32 uint2 per 128-elem row
            *reinterpret_cast<uint2*>(sm + OFF_BH + r*ROWB + c*8) = sh[idx];
            *reinterpret_cast<uint2*>(sm + OFF_BL + r*ROWB + c*8) = sl[idx];
        }
    }

    // ---- A tile: coalesced load, split to bf16 hi/lo, padded smem ----
    {
        const float4* gA = reinterpret_cast<const float4*>(A);
        #pragma unroll 4
        for (int i = 0; i < 16; i++) {
            int lin = tid + i*256;            // 4096 float4
            int r = lin >> 5, d4 = lin & 31;
            int gr = r0 + r; if (gr >= NROW) gr = NROW - 1;
            float4 a = gA[(size_t)gr*32 + d4];
            __nv_bfloat162 h01 = __floats2bfloat162_rn(a.x, a.y);
            __nv_bfloat162 h23 = __floats2bfloat162_rn(a.z, a.w);
            float l0 = a.x - __bfloat162float(h01.x);
            float l1 = a.y - __bfloat162float(h01.y);
            float l2 = a.z - __bfloat162float(h23.x);
            float l3 = a.w - __bfloat162float(h23.y);
            __nv_bfloat162 q01 = __floats2bfloat162_rn(l0, l1);
            __nv_bfloat162 q23 = __floats2bfloat162_rn(l2, l3);
            uint32_t doff = r*ROWB + d4*8;
            *reinterpret_cast<uint2*>(sm + OFF_AH + doff) =
                make_uint2(*reinterpret_cast<uint32_t*>(&h01), *reinterpret_cast<uint32_t*>(&h23));
            *reinterpret_cast<uint2*>(sm + OFF_AL + doff) =
                make_uint2(*reinterpret_cast<uint32_t*>(&q01), *reinterpret_cast<uint32_t*>(&q23));
        }
    }
    __syncthreads();

    // ---- fragment compute: warp tile 32(m) x 32(n) ----
    int wm = (warp & 3) * 32;
    int wn = (warp >> 2) * 32;

    // ldmatrix lane addressing (byte offsets within a tile)
    uint32_t aoff = (uint32_t)(wm + (lane & 15)) * ROWB + ((lane >> 4) * 8) * 2;
    uint32_t boff = (uint32_t)(wn + (lane & 7) + ((lane >> 4) << 3)) * ROWB
                  + (((lane >> 3) & 1) * 8) * 2;

    float dacc[2][4][4];
    #pragma unroll
    for (int mb = 0; mb < 2; mb++)
        #pragma unroll
        for (int nb = 0; nb < 4; nb++)
            #pragma unroll
            for (int e = 0; e < 4; e++) dacc[mb][nb][e] = 0.f;

    #pragma unroll
    for (int t = 0; t < 3; t++) {
        uint32_t abase = base_u + (t == 2 ? OFF_AL : OFF_AH) + aoff;
        uint32_t bbase = base_u + (t == 1 ? OFF_BL : OFF_BH) + boff;
        #pragma unroll
        for (int ks = 0; ks < 8; ks++) {
            uint32_t ak = abase + ks*32;
            uint32_t bk = bbase + ks*32;
            uint32_t a0[4], a1[4], b0[4], b1[4];
            ldmx4(a0, ak);
            ldmx4(a1, ak + 16*ROWB);
            ldmx4(b0, bk);               // n-blocks 0,1
            ldmx4(b1, bk + 16*ROWB);     // n-blocks 2,3
            mma16816(dacc[0][0], a0, b0[0], b0[1]);
            mma16816(dacc[0][1], a0, b0[2], b0[3]);
            mma16816(dacc[0][2], a0, b1[0], b1[1]);
            mma16816(dacc[0][3], a0, b1[2], b1[3]);
            mma16816(dacc[1][0], a1, b0[0], b0[1]);
            mma16816(dacc[1][1], a1, b0[2], b0[3]);
            mma16816(dacc[1][2], a1, b1[0], b1[1]);
            mma16816(dacc[1][3], a1, b1[2], b1[3]);
        }
    }
    __syncthreads();   // done reading A/B smem; reuse for epilogue

    // ---- epilogue: regs -> padded smem -> coalesced STG ----
    float* stg = reinterpret_cast<float*>(sm);   // 128*65*4 = 33280 B
    #pragma unroll
    for (int mb = 0; mb < 2; mb++) {
        #pragma unroll
        for (int nb = 0; nb < 4; nb++) {
            int row = wm + mb*16 + (lane >> 2);
            int col = wn + nb*8 + (lane & 3)*2;
            stg[row*65 + col]       = dacc[mb][nb][0];
            stg[row*65 + col + 1]   = dacc[mb][nb][1];
            stg[(row+8)*65 + col]   = dacc[mb][nb][2];
            stg[(row+8)*65 + col+1] = dacc[mb][nb][3];
        }
    }
    __syncthreads();

    float* Sout = g_S[side];
    #pragma unroll 8
    for (int j = 0; j < 32; j++) {
        int o = tid + j*256;
        int r = o >> 6, c = o & 63;
        if (r0 + r < NROW)
            Sout[(size_t)r0*64 + o] = stg[r*65 + c];
    }
}

// ---------------- K4: gather + exp + Z partials (both sides) ----------------
__global__ void gather_kernel(const int* __restrict__ idx, const int* __restrict__ cidx) {
    int b = blockIdx.y, bx = blockIdx.x;
    int t = threadIdx.x;
    const float* S0 = g_S[0];
    const float* S1 = g_S[1];
    float sum0 = 0.f, sum1 = 0.f;
    #pragma unroll
    for (int i = 0; i < 8; i++) {
        int k = bx*2048 + i*256 + t;
        if (k < KP1) {
            int row = (k == 0) ? idx[b] : cidx[b*KP1 + k];
            size_t off = (size_t)row * BATCH + b;
            float e0 = expf(S0[off] * INV_T);
            float e1 = expf(S1[off] * INV_T);
            g_e[0][b*KP1 + k] = e0;
            g_e[1][b*KP1 + k] = e1;
            sum0 += e0;
            sum1 += e1;
        }
    }
    float t0 = block_reduce_256(sum0);
    float t1 = block_reduce_256(sum1);
    if (t == 0) { g_pZ[0][b*NBX + bx] = t0; g_pZ[1][b*NBX + bx] = t1; }
}

// ---------------- K5: loss partials ----------------
__global__ void loss_kernel() {
    int b = blockIdx.y, bx = blockIdx.x;
    int t = threadIdx.x;

    float z0 = 0.f, z1 = 0.f;
    for (int i = t; i < NPART; i += 256) { z0 += g_pZ[0][i]; z1 += g_pZ[1][i]; }
    float zt0 = block_reduce_256(z0);
    float zt1 = block_reduce_256(z1);
    float invZ0 = 1.0f / ((zt0 / (float)NELEM) * (float)NROW);
    float invZ1 = 1.0f / ((zt1 / (float)NELEM) * (float)NROW);

    float acc = 0.f;
    #pragma unroll
    for (int i = 0; i < 8; i++) {
        int k = bx*2048 + i*256 + t;
        if (k < KP1) {
            float x0 = g_e[0][b*KP1 + k] * invZ0;
            float x1 = g_e[1][b*KP1 + k] * invZ1;
            if (k == 0) acc += log1pf(CCONST / x0) + log1pf(CCONST / x1);
            else        acc += log1pf((x0 + EPSC) / MPN) + log1pf((x1 + EPSC) / MPN);
        }
    }
    float tot = block_reduce_256(acc);
    if (t == 0) g_pL[b*NBX + bx] = tot;
}

// ---------------- K6: final scalar ----------------
__global__ void final_kernel(float* __restrict__ out) {
    int t = threadIdx.x;
    float s = 0.f;
    for (int i = t; i < NPART; i += 256) s += g_pL[i];
    float tot = block_reduce_256(s);
    if (t == 0) out[0] = tot / (float)BATCH;
}

// ---------------- launch ----------------
extern "C" void kernel_launch(void* const* d_in, const int* in_sizes, int n_in,
                              void* d_out, int out_size) {
    const float* f_s  = (const float*)d_in[0];
    const float* f_t  = (const float*)d_in[1];
    const int*   idx  = (const int*)  d_in[2];
    const int*   cidx = (const int*)  d_in[3];
    const float* Ws   = (const float*)d_in[4];
    const float* bs   = (const float*)d_in[5];
    const float* Wt   = (const float*)d_in[6];
    const float* bt   = (const float*)d_in[7];
    const float* mem1 = (const float*)d_in[8];
    const float* mem2 = (const float*)d_in[9];

    cudaFuncSetAttribute(gemm_mma, cudaFuncAttributeMaxDynamicSharedMemorySize, SMEM_DYN);

    embed_kernel <<<dim3(16, 2),       256>>>(f_s, f_t, Ws, Wt);
    norm_kernel  <<<dim3(BATCH, 2),    128>>>(bs, bt);
    prep_kernel  <<<1, 32>>>();
    gemm_mma     <<<dim3(782, 2),      256, SMEM_DYN>>>(mem1, mem2);
    gather_kernel<<<dim3(NBX, BATCH),  256>>>(idx, cidx);
    loss_kernel  <<<dim3(NBX, BATCH),  256>>>();
    final_kernel <<<1,                 256>>>((float*)d_out);
}

// round 5
// speedup vs baseline: 3.1202x; 1.1335x over previous
#include <cuda_runtime.h>
#include <cuda_bf16.h>
#include <cstdint>
#include <math.h>

#define NROW   100000
#define FD     128
#define BATCH  64
#define KP1    16385
#define NELEM  (BATCH*KP1)        // 1048640
#define INV_T  (1.0f/0.07f)
#define EPSC   1e-7f
#define MPN    0.16384f           // 16384/100000
#define CCONST (MPN + EPSC)
#define NBX    17
#define NPART  (BATCH*NBX)        // 1088

// ---- gemm smem layout (bf16 tiles, rows padded to 136 elems = 272B) ----
#define ROWB   272                 // bytes per padded row
#define OFF_AH 0                   // 128 x 272B = 34816
#define OFF_AL 34816
#define OFF_BH 69632               // 64 x 272B = 17408
#define OFF_BL 87040
#define SMEM_DYN 104448

// ---------------- scratch (device globals; no allocation) ----------------
__device__ float g_yp[4][2*BATCH*FD];                      // embed split-k partials
__device__ __align__(16) __nv_bfloat16 g_Bh[2][BATCH*FD];  // v hi, [side][b*128+d]
__device__ __align__(16) __nv_bfloat16 g_Bl[2][BATCH*FD];  // v lo
__device__ float g_S [2][6400000];                         // [side][row*64+b]
__device__ float g_e [2][NELEM];
__device__ float g_pZ[2][NPART];
__device__ float g_pL[NPART];
__device__ float g_pad;

// =================== portable PTX helpers (sm_80+ features) ===================
__device__ __forceinline__ uint32_t smem_u32(const void* p) {
    uint32_t a;
    asm("{ .reg .u64 t; cvta.to.shared.u64 t, %1; cvt.u32.u64 %0, t; }" : "=r"(a) : "l"(p));
    return a;
}
__device__ __forceinline__ void ldmx4(uint32_t* r, uint32_t addr) {
    asm volatile("ldmatrix.sync.aligned.m8n8.x4.shared.b16 {%0,%1,%2,%3}, [%4];"
                 : "=r"(r[0]), "=r"(r[1]), "=r"(r[2]), "=r"(r[3]) : "r"(addr));
}
__device__ __forceinline__ void mma16816(float* d, const uint32_t* a,
                                         uint32_t b0, uint32_t b1) {
    asm volatile(
        "mma.sync.aligned.m16n8k16.row.col.f32.bf16.bf16.f32 "
        "{%0,%1,%2,%3}, {%4,%5,%6,%7}, {%8,%9}, {%0,%1,%2,%3};"
        : "+f"(d[0]), "+f"(d[1]), "+f"(d[2]), "+f"(d[3])
        : "r"(a[0]), "r"(a[1]), "r"(a[2]), "r"(a[3]), "r"(b0), "r"(b1));
}

// ---------------- deterministic reductions ----------------
__device__ __forceinline__ float block_reduce_256(float v) {
    __shared__ float sh[8];
    #pragma unroll
    for (int o = 16; o > 0; o >>= 1) v += __shfl_xor_sync(0xffffffffu, v, o);
    __syncthreads();
    if ((threadIdx.x & 31) == 0) sh[threadIdx.x >> 5] = v;
    __syncthreads();
    float t = 0.f;
    #pragma unroll
    for (int i = 0; i < 8; i++) t += sh[i];
    return t;
}

// ---------------- K0: embed GEMM split-k  y_partial = f @ W^T ----------------
__global__ void embed_kernel(const float* __restrict__ f_s, const float* __restrict__ f_t,
                             const float* __restrict__ Ws,  const float* __restrict__ Wt) {
    int side = blockIdx.y;
    int ft = blockIdx.x & 3;
    int kc = blockIdx.x >> 2;
    const float* f = side ? f_t : f_s;
    const float* W = side ? Wt  : Ws;
    int dim  = side ? 2048 : 1024;
    int klen = dim >> 2;
    int kbeg = kc * klen;

    __shared__ float Fs[64][65];
    __shared__ float Wc[32][65];

    int tid = threadIdx.x;
    int tx  = tid & 31;
    int bg  = tid >> 5;
    int ftb = ft * 32;

    float acc[8] = {0.f,0.f,0.f,0.f,0.f,0.f,0.f,0.f};

    for (int k0 = kbeg; k0 < kbeg + klen; k0 += 64) {
        for (int i = tid; i < 64*64; i += 256) {
            int bb = i >> 6, kk = i & 63;
            Fs[bb][kk] = f[bb*dim + k0 + kk];
        }
        for (int i = tid; i < 32*64; i += 256) {
            int r = i >> 6, kk = i & 63;
            Wc[r][kk] = W[(ftb + r)*dim + k0 + kk];
        }
        __syncthreads();
        #pragma unroll 8
        for (int kk = 0; kk < 64; kk++) {
            float w = Wc[tx][kk];
            #pragma unroll
            for (int j = 0; j < 8; j++) acc[j] += Fs[bg*8 + j][kk] * w;
        }
        __syncthreads();
    }
    #pragma unroll
    for (int j = 0; j < 8; j++)
        g_yp[kc][side*BATCH*FD + (bg*8 + j)*FD + ftb + tx] = acc[j];
}

// ---------------- K1: sum partials + bias + l2norm + bf16 hi/lo B ----------------
__global__ void norm_kernel(const float* __restrict__ bs, const float* __restrict__ bt) {
    int side = blockIdx.y, b = blockIdx.x, d = threadIdx.x;
    const float* bias = side ? bt : bs;
    int o = side*BATCH*FD + b*FD + d;
    float y = g_yp[0][o] + g_yp[1][o] + g_yp[2][o] + g_yp[3][o] + bias[d];
    float s = y * y;
    #pragma unroll
    for (int of = 16; of > 0; of >>= 1) s += __shfl_xor_sync(0xffffffffu, s, of);
    __shared__ float sh[4];
    if ((d & 31) == 0) sh[d >> 5] = s;
    __syncthreads();
    float inv = rsqrtf(sh[0] + sh[1] + sh[2] + sh[3]);
    float v = y * inv;

    __nv_bfloat16 hi = __float2bfloat16_rn(v);
    __nv_bfloat16 lo = __float2bfloat16_rn(v - __bfloat162float(hi));
    g_Bh[side][b*FD + d] = hi;
    g_Bl[side][b*FD + d] = lo;
}

// ---------------- K2: trivial (keeps gemm at the profiled slot) ----------------
__global__ void prep_kernel() {
    if (threadIdx.x == 0 && blockIdx.x == 0) g_pad = 0.f;
}

// ---------------- K3: tensor GEMM, K-split pipelined ----------------
// S[r][b] = dot(memory[r], v[b]); per CTA 128 rows x 64 cols x K=128.
__global__ void __launch_bounds__(256, 2)
gemm_mma(const float* __restrict__ mem1, const float* __restrict__ mem2) {
    int side = blockIdx.y;
    const float* A = side ? mem1 : mem2;
    int r0 = blockIdx.x * 128;

    extern __shared__ __align__(16) unsigned char sm[];
    uint32_t base_u = smem_u32(sm);

    int tid  = threadIdx.x;
    int lane = tid & 31;
    int warp = tid >> 5;

    // ---- B tiles: copy pre-split hi/lo [64][128] into padded smem ----
    {
        const uint2* shp = reinterpret_cast<const uint2*>(&g_Bh[side][0]);
        const uint2* slp = reinterpret_cast<const uint2*>(&g_Bl[side][0]);
        #pragma unroll
        for (int i = 0; i < 8; i++) {
            int idx = tid + i*256;            // 2048 uint2 per tile
            int r = idx >> 5, c = idx & 31;
            *reinterpret_cast<uint2*>(sm + OFF_BH + r*ROWB + c*8) = shp[idx];
            *reinterpret_cast<uint2*>(sm + OFF_BL + r*ROWB + c*8) = slp[idx];
        }
    }

    const float4* gA = reinterpret_cast<const float4*>(A);

    // ---- A half0 (K cols 0..63): load, split, STS ----
    #pragma unroll
    for (int i = 0; i < 8; i++) {
        int lin = tid + i*256;                // 2048 float4 per half
        int r = lin >> 4, d4 = lin & 15;
        int gr = r0 + r; if (gr >= NROW) gr = NROW - 1;
        float4 a = gA[(size_t)gr*32 + d4];
        __nv_bfloat162 h01 = __floats2bfloat162_rn(a.x, a.y);
        __nv_bfloat162 h23 = __floats2bfloat162_rn(a.z, a.w);
        __nv_bfloat162 q01 = __floats2bfloat162_rn(a.x - __bfloat162float(h01.x),
                                                   a.y - __bfloat162float(h01.y));
        __nv_bfloat162 q23 = __floats2bfloat162_rn(a.z - __bfloat162float(h23.x),
                                                   a.w - __bfloat162float(h23.y));
        uint32_t doff = r*ROWB + d4*8;
        *reinterpret_cast<uint2*>(sm + OFF_AH + doff) =
            make_uint2(*reinterpret_cast<uint32_t*>(&h01), *reinterpret_cast<uint32_t*>(&h23));
        *reinterpret_cast<uint2*>(sm + OFF_AL + doff) =
            make_uint2(*reinterpret_cast<uint32_t*>(&q01), *reinterpret_cast<uint32_t*>(&q23));
    }
    __syncthreads();

    // ---- issue A half1 loads (in flight during half0 compute) ----
    float4 a1[8];
    #pragma unroll
    for (int i = 0; i < 8; i++) {
        int lin = tid + i*256;
        int r = lin >> 4, d4 = lin & 15;
        int gr = r0 + r; if (gr >= NROW) gr = NROW - 1;
        a1[i] = gA[(size_t)gr*32 + 16 + d4];
    }

    // ---- fragment setup: warp tile 32(m) x 32(n) ----
    int wm = (warp & 3) * 32;
    int wn = (warp >> 2) * 32;
    uint32_t aoff = (uint32_t)(wm + (lane & 15)) * ROWB + ((lane >> 4) * 8) * 2;
    uint32_t boff = (uint32_t)(wn + (lane & 7) + ((lane >> 4) << 3)) * ROWB
                  + (((lane >> 3) & 1) * 8) * 2;

    float dacc[2][4][4];
    #pragma unroll
    for (int mb = 0; mb < 2; mb++)
        #pragma unroll
        for (int nb = 0; nb < 4; nb++)
            #pragma unroll
            for (int e = 0; e < 4; e++) dacc[mb][nb][e] = 0.f;

#define COMPUTE_HALF(KB)                                                      \
    _Pragma("unroll")                                                         \
    for (int t = 0; t < 3; t++) {                                             \
        uint32_t abase = base_u + (t == 2 ? OFF_AL : OFF_AH) + aoff;          \
        uint32_t bbase = base_u + (t == 1 ? OFF_BL : OFF_BH) + boff;          \
        _Pragma("unroll")                                                     \
        for (int ks = (KB); ks < (KB) + 4; ks++) {                            \
            uint32_t ak = abase + ks*32;                                      \
            uint32_t bk = bbase + ks*32;                                      \
            uint32_t fa0[4], fa1[4], fb0[4], fb1[4];                          \
            ldmx4(fa0, ak);                                                   \
            ldmx4(fa1, ak + 16*ROWB);                                         \
            ldmx4(fb0, bk);                                                   \
            ldmx4(fb1, bk + 16*ROWB);                                         \
            mma16816(dacc[0][0], fa0, fb0[0], fb0[1]);                        \
            mma16816(dacc[0][1], fa0, fb0[2], fb0[3]);                        \
            mma16816(dacc[0][2], fa0, fb1[0], fb1[1]);                        \
            mma16816(dacc[0][3], fa0, fb1[2], fb1[3]);                        \
            mma16816(dacc[1][0], fa1, fb0[0], fb0[1]);                        \
            mma16816(dacc[1][1], fa1, fb0[2], fb0[3]);                        \
            mma16816(dacc[1][2], fa1, fb1[0], fb1[1]);                        \
            mma16816(dacc[1][3], fa1, fb1[2], fb1[3]);                        \
        }                                                                     \
    }

    COMPUTE_HALF(0)

    // ---- split + STS half1 (disjoint bytes vs half0 readers) ----
    #pragma unroll
    for (int i = 0; i < 8; i++) {
        int lin = tid + i*256;
        int r = lin >> 4, d4 = lin & 15;
        float4 a = a1[i];
        __nv_bfloat162 h01 = __floats2bfloat162_rn(a.x, a.y);
        __nv_bfloat162 h23 = __floats2bfloat162_rn(a.z, a.w);
        __nv_bfloat162 q01 = __floats2bfloat162_rn(a.x - __bfloat162float(h01.x),
                                                   a.y - __bfloat162float(h01.y));
        __nv_bfloat162 q23 = __floats2bfloat162_rn(a.z - __bfloat162float(h23.x),
                                                   a.w - __bfloat162float(h23.y));
        uint32_t doff = r*ROWB + 128 + d4*8;
        *reinterpret_cast<uint2*>(sm + OFF_AH + doff) =
            make_uint2(*reinterpret_cast<uint32_t*>(&h01), *reinterpret_cast<uint32_t*>(&h23));
        *reinterpret_cast<uint2*>(sm + OFF_AL + doff) =
            make_uint2(*reinterpret_cast<uint32_t*>(&q01), *reinterpret_cast<uint32_t*>(&q23));
    }
    __syncthreads();

    COMPUTE_HALF(4)
#undef COMPUTE_HALF

    // ---- epilogue: direct fragment -> STG.64 (no smem round-trip) ----
    float* Sout = g_S[side];
    #pragma unroll
    for (int mb = 0; mb < 2; mb++) {
        #pragma unroll
        for (int nb = 0; nb < 4; nb++) {
            int row = r0 + wm + mb*16 + (lane >> 2);
            int col = wn + nb*8 + (lane & 3)*2;
            if (row < NROW)
                *reinterpret_cast<float2*>(&Sout[(size_t)row*64 + col]) =
                    make_float2(dacc[mb][nb][0], dacc[mb][nb][1]);
            if (row + 8 < NROW)
                *reinterpret_cast<float2*>(&Sout[(size_t)(row+8)*64 + col]) =
                    make_float2(dacc[mb][nb][2], dacc[mb][nb][3]);
        }
    }
}

// ---------------- K4: gather + exp + Z partials (both sides) ----------------
__global__ void gather_kernel(const int* __restrict__ idx, const int* __restrict__ cidx) {
    int b = blockIdx.y, bx = blockIdx.x;
    int t = threadIdx.x;
    const float* S0 = g_S[0];
    const float* S1 = g_S[1];
    float sum0 = 0.f, sum1 = 0.f;
    #pragma unroll
    for (int i = 0; i < 4; i++) {
        int k = bx*1024 + i*256 + t;
        if (k < KP1) {
            int row = (k == 0) ? idx[b] : cidx[b*KP1 + k];
            size_t off = (size_t)row * BATCH + b;
            float e0 = expf(S0[off] * INV_T);
            float e1 = expf(S1[off] * INV_T);
            g_e[0][b*KP1 + k] = e0;
            g_e[1][b*KP1 + k] = e1;
            sum0 += e0;
            sum1 += e1;
        }
    }
    float t0 = block_reduce_256(sum0);
    float t1 = block_reduce_256(sum1);
    if (t == 0) { g_pZ[0][b*NBX + bx] = t0; g_pZ[1][b*NBX + bx] = t1; }
}

// ---------------- K5: loss partials ----------------
__global__ void loss_kernel() {
    int b = blockIdx.y, bx = blockIdx.x;
    int t = threadIdx.x;

    float z0 = 0.f, z1 = 0.f;
    for (int i = t; i < NPART; i += 256) { z0 += g_pZ[0][i]; z1 += g_pZ[1][i]; }
    float zt0 = block_reduce_256(z0);
    float zt1 = block_reduce_256(z1);
    float invZ0 = 1.0f / ((zt0 / (float)NELEM) * (float)NROW);
    float invZ1 = 1.0f / ((zt1 / (float)NELEM) * (float)NROW);

    float acc = 0.f;
    #pragma unroll
    for (int i = 0; i < 4; i++) {
        int k = bx*1024 + i*256 + t;
        if (k < KP1) {
            float x0 = g_e[0][b*KP1 + k] * invZ0;
            float x1 = g_e[1][b*KP1 + k] * invZ1;
            if (k == 0) acc += log1pf(CCONST / x0) + log1pf(CCONST / x1);
            else        acc += log1pf((x0 + EPSC) / MPN) + log1pf((x1 + EPSC) / MPN);
        }
    }
    float tot = block_reduce_256(acc);
    if (t == 0) g_pL[b*NBX + bx] = tot;
}

// ---------------- K6: final scalar ----------------
__global__ void final_kernel(float* __restrict__ out) {
    int t = threadIdx.x;
    float s = 0.f;
    for (int i = t; i < NPART; i += 256) s += g_pL[i];
    float tot = block_reduce_256(s);
    if (t == 0) out[0] = tot / (float)BATCH;
}

// ---------------- launch ----------------
extern "C" void kernel_launch(void* const* d_in, const int* in_sizes, int n_in,
                              void* d_out, int out_size) {
    const float* f_s  = (const float*)d_in[0];
    const float* f_t  = (const float*)d_in[1];
    const int*   idx  = (const int*)  d_in[2];
    const int*   cidx = (const int*)  d_in[3];
    const float* Ws   = (const float*)d_in[4];
    const float* bs   = (const float*)d_in[5];
    const float* Wt   = (const float*)d_in[6];
    const float* bt   = (const float*)d_in[7];
    const float* mem1 = (const float*)d_in[8];
    const float* mem2 = (const float*)d_in[9];

    cudaFuncSetAttribute(gemm_mma, cudaFuncAttributeMaxDynamicSharedMemorySize, SMEM_DYN);

    embed_kernel <<<dim3(16, 2),       256>>>(f_s, f_t, Ws, Wt);
    norm_kernel  <<<dim3(BATCH, 2),    128>>>(bs, bt);
    prep_kernel  <<<1, 32>>>();
    gemm_mma     <<<dim3(782, 2),      256, SMEM_DYN>>>(mem1, mem2);
    gather_kernel<<<dim3(NBX, BATCH),  256>>>(idx, cidx);
    loss_kernel  <<<dim3(NBX, BATCH),  256>>>();
    final_kernel <<<1,                 256>>>((float*)d_out);
}

// round 6
// speedup vs baseline: 3.2727x; 1.0489x over previous
#include <cuda_runtime.h>
#include <cuda_bf16.h>
#include <cstdint>
#include <math.h>

#define NROW   100000
#define FD     128
#define BATCH  64
#define KP1    16385
#define NELEM  (BATCH*KP1)        // 1048640
#define INV_T  (1.0f/0.07f)
#define EPSC   1e-7f
#define MPN    0.16384f           // 16384/100000
#define CCONST (MPN + EPSC)
#define NBX    17
#define NPART  (BATCH*NBX)        // 1088

// ---- gemm smem layout (bf16 tiles, rows padded to 136 elems = 272B) ----
#define ROWB   272                 // bytes per padded row
#define OFF_AH 0                   // 128 x 272B = 34816
#define OFF_AL 34816
#define OFF_BH 69632               // 64 x 272B = 17408
#define OFF_BL 87040
#define SMEM_DYN 104448

// ---------------- scratch (device globals; no allocation) ----------------
__device__ float g_yp[4][2*BATCH*FD];                      // embed split-k partials
__device__ __align__(16) __nv_bfloat16 g_Bh[2][BATCH*FD];  // v hi, [side][b*128+d]
__device__ __align__(16) __nv_bfloat16 g_Bl[2][BATCH*FD];  // v lo
__device__ float g_S [2][6400000];                         // [side][row*64+b]
__device__ float g_e [2][NELEM];
__device__ float g_pZ[2][NPART];
__device__ float g_pL[NPART];
__device__ float g_pad;

// =================== portable PTX helpers (sm_80+ features) ===================
__device__ __forceinline__ uint32_t smem_u32(const void* p) {
    uint32_t a;
    asm("{ .reg .u64 t; cvta.to.shared.u64 t, %1; cvt.u32.u64 %0, t; }" : "=r"(a) : "l"(p));
    return a;
}
__device__ __forceinline__ void ldmx4(uint32_t* r, uint32_t addr) {
    asm volatile("ldmatrix.sync.aligned.m8n8.x4.shared.b16 {%0,%1,%2,%3}, [%4];"
                 : "=r"(r[0]), "=r"(r[1]), "=r"(r[2]), "=r"(r[3]) : "r"(addr));
}
__device__ __forceinline__ void mma16816(float* d, const uint32_t* a,
                                         uint32_t b0, uint32_t b1) {
    asm volatile(
        "mma.sync.aligned.m16n8k16.row.col.f32.bf16.bf16.f32 "
        "{%0,%1,%2,%3}, {%4,%5,%6,%7}, {%8,%9}, {%0,%1,%2,%3};"
        : "+f"(d[0]), "+f"(d[1]), "+f"(d[2]), "+f"(d[3])
        : "r"(a[0]), "r"(a[1]), "r"(a[2]), "r"(a[3]), "r"(b0), "r"(b1));
}

// ---------------- deterministic reductions ----------------
__device__ __forceinline__ float block_reduce_256(float v) {
    __shared__ float sh[8];
    #pragma unroll
    for (int o = 16; o > 0; o >>= 1) v += __shfl_xor_sync(0xffffffffu, v, o);
    __syncthreads();
    if ((threadIdx.x & 31) == 0) sh[threadIdx.x >> 5] = v;
    __syncthreads();
    float t = 0.f;
    #pragma unroll
    for (int i = 0; i < 8; i++) t += sh[i];
    return t;
}

// ---------------- K0: embed GEMM split-k  y_partial = f @ W^T ----------------
__global__ void embed_kernel(const float* __restrict__ f_s, const float* __restrict__ f_t,
                             const float* __restrict__ Ws,  const float* __restrict__ Wt) {
    int side = blockIdx.y;
    int ft = blockIdx.x & 3;
    int kc = blockIdx.x >> 2;
    const float* f = side ? f_t : f_s;
    const float* W = side ? Wt  : Ws;
    int dim  = side ? 2048 : 1024;
    int klen = dim >> 2;
    int kbeg = kc * klen;

    __shared__ float Fs[64][65];
    __shared__ float Wc[32][65];

    int tid = threadIdx.x;
    int tx  = tid & 31;
    int bg  = tid >> 5;
    int ftb = ft * 32;

    float acc[8] = {0.f,0.f,0.f,0.f,0.f,0.f,0.f,0.f};

    for (int k0 = kbeg; k0 < kbeg + klen; k0 += 64) {
        for (int i = tid; i < 64*64; i += 256) {
            int bb = i >> 6, kk = i & 63;
            Fs[bb][kk] = f[bb*dim + k0 + kk];
        }
        for (int i = tid; i < 32*64; i += 256) {
            int r = i >> 6, kk = i & 63;
            Wc[r][kk] = W[(ftb + r)*dim + k0 + kk];
        }
        __syncthreads();
        #pragma unroll 8
        for (int kk = 0; kk < 64; kk++) {
            float w = Wc[tx][kk];
            #pragma unroll
            for (int j = 0; j < 8; j++) acc[j] += Fs[bg*8 + j][kk] * w;
        }
        __syncthreads();
    }
    #pragma unroll
    for (int j = 0; j < 8; j++)
        g_yp[kc][side*BATCH*FD + (bg*8 + j)*FD + ftb + tx] = acc[j];
}

// ---------------- K1: sum partials + bias + l2norm + bf16 hi/lo B ----------------
__global__ void norm_kernel(const float* __restrict__ bs, const float* __restrict__ bt) {
    int side = blockIdx.y, b = blockIdx.x, d = threadIdx.x;
    const float* bias = side ? bt : bs;
    int o = side*BATCH*FD + b*FD + d;
    float y = g_yp[0][o] + g_yp[1][o] + g_yp[2][o] + g_yp[3][o] + bias[d];
    float s = y * y;
    #pragma unroll
    for (int of = 16; of > 0; of >>= 1) s += __shfl_xor_sync(0xffffffffu, s, of);
    __shared__ float sh[4];
    if ((d & 31) == 0) sh[d >> 5] = s;
    __syncthreads();
    float inv = rsqrtf(sh[0] + sh[1] + sh[2] + sh[3]);
    float v = y * inv;

    __nv_bfloat16 hi = __float2bfloat16_rn(v);
    __nv_bfloat16 lo = __float2bfloat16_rn(v - __bfloat162float(hi));
    g_Bh[side][b*FD + d] = hi;
    g_Bl[side][b*FD + d] = lo;
}

// ---------------- K2: trivial (keeps gemm at the profiled slot) ----------------
__global__ void prep_kernel() {
    if (threadIdx.x == 0 && blockIdx.x == 0) g_pad = 0.f;
}

// ---------------- K3: tensor GEMM, K-split pipelined, fused fragments ----------------
// S[r][b] = dot(memory[r], v[b]); per CTA 128 rows x 64 cols x K=128.
__global__ void __launch_bounds__(256, 2)
gemm_mma(const float* __restrict__ mem1, const float* __restrict__ mem2) {
    int side = blockIdx.y;
    const float* A = side ? mem1 : mem2;
    int r0 = blockIdx.x * 128;

    extern __shared__ __align__(16) unsigned char sm[];
    uint32_t base_u = smem_u32(sm);

    int tid  = threadIdx.x;
    int lane = tid & 31;
    int warp = tid >> 5;

    // ---- B tiles: copy pre-split hi/lo [64][128] into padded smem ----
    {
        const uint2* shp = reinterpret_cast<const uint2*>(&g_Bh[side][0]);
        const uint2* slp = reinterpret_cast<const uint2*>(&g_Bl[side][0]);
        #pragma unroll
        for (int i = 0; i < 8; i++) {
            int idx = tid + i*256;            // 2048 uint2 per tile
            int r = idx >> 5, c = idx & 31;
            *reinterpret_cast<uint2*>(sm + OFF_BH + r*ROWB + c*8) = shp[idx];
            *reinterpret_cast<uint2*>(sm + OFF_BL + r*ROWB + c*8) = slp[idx];
        }
    }

    const float4* gA = reinterpret_cast<const float4*>(A);

    // ---- A half0 (K cols 0..63): load, split, STS ----
    #pragma unroll
    for (int i = 0; i < 8; i++) {
        int lin = tid + i*256;                // 2048 float4 per half
        int r = lin >> 4, d4 = lin & 15;
        int gr = r0 + r; if (gr >= NROW) gr = NROW - 1;
        float4 a = gA[(size_t)gr*32 + d4];
        __nv_bfloat162 h01 = __floats2bfloat162_rn(a.x, a.y);
        __nv_bfloat162 h23 = __floats2bfloat162_rn(a.z, a.w);
        __nv_bfloat162 q01 = __floats2bfloat162_rn(a.x - __bfloat162float(h01.x),
                                                   a.y - __bfloat162float(h01.y));
        __nv_bfloat162 q23 = __floats2bfloat162_rn(a.z - __bfloat162float(h23.x),
                                                   a.w - __bfloat162float(h23.y));
        uint32_t doff = r*ROWB + d4*8;
        *reinterpret_cast<uint2*>(sm + OFF_AH + doff) =
            make_uint2(*reinterpret_cast<uint32_t*>(&h01), *reinterpret_cast<uint32_t*>(&h23));
        *reinterpret_cast<uint2*>(sm + OFF_AL + doff) =
            make_uint2(*reinterpret_cast<uint32_t*>(&q01), *reinterpret_cast<uint32_t*>(&q23));
    }

    // ---- issue A half1 loads BEFORE the barrier (max overlap) ----
    float4 a1[8];
    #pragma unroll
    for (int i = 0; i < 8; i++) {
        int lin = tid + i*256;
        int r = lin >> 4, d4 = lin & 15;
        int gr = r0 + r; if (gr >= NROW) gr = NROW - 1;
        a1[i] = gA[(size_t)gr*32 + 16 + d4];
    }
    __syncthreads();

    // ---- fragment setup: warp tile 32(m) x 32(n) ----
    int wm = (warp & 3) * 32;
    int wn = (warp >> 2) * 32;
    uint32_t aoff = (uint32_t)(wm + (lane & 15)) * ROWB + ((lane >> 4) * 8) * 2;
    uint32_t boff = (uint32_t)(wn + (lane & 7) + ((lane >> 4) << 3)) * ROWB
                  + (((lane >> 3) & 1) * 8) * 2;

    float dacc[2][4][4];
    #pragma unroll
    for (int mb = 0; mb < 2; mb++)
        #pragma unroll
        for (int nb = 0; nb < 4; nb++)
            #pragma unroll
            for (int e = 0; e < 4; e++) dacc[mb][nb][e] = 0.f;

    // fused-fragment compute: per k-step load Ah/Al/Bh/Bl once, 24 MMAs
#define COMPUTE_HALF(KB)                                                      \
    _Pragma("unroll")                                                         \
    for (int ks = (KB); ks < (KB) + 4; ks++) {                                \
        uint32_t ahk = base_u + OFF_AH + aoff + ks*32;                        \
        uint32_t alk = base_u + OFF_AL + aoff + ks*32;                        \
        uint32_t bhk = base_u + OFF_BH + boff + ks*32;                        \
        uint32_t blk = base_u + OFF_BL + boff + ks*32;                        \
        uint32_t ah0[4], ah1[4], al0[4], al1[4];                              \
        uint32_t bh0[4], bh1[4], bl0[4], bl1[4];                              \
        ldmx4(ah0, ahk);                                                      \
        ldmx4(ah1, ahk + 16*ROWB);                                            \
        ldmx4(bh0, bhk);                                                      \
        ldmx4(bh1, bhk + 16*ROWB);                                            \
        ldmx4(al0, alk);                                                      \
        ldmx4(al1, alk + 16*ROWB);                                            \
        ldmx4(bl0, blk);                                                      \
        ldmx4(bl1, blk + 16*ROWB);                                            \
        mma16816(dacc[0][0], ah0, bh0[0], bh0[1]);                            \
        mma16816(dacc[0][1], ah0, bh0[2], bh0[3]);                            \
        mma16816(dacc[0][2], ah0, bh1[0], bh1[1]);                            \
        mma16816(dacc[0][3], ah0, bh1[2], bh1[3]);                            \
        mma16816(dacc[1][0], ah1, bh0[0], bh0[1]);                            \
        mma16816(dacc[1][1], ah1, bh0[2], bh0[3]);                            \
        mma16816(dacc[1][2], ah1, bh1[0], bh1[1]);                            \
        mma16816(dacc[1][3], ah1, bh1[2], bh1[3]);                            \
        mma16816(dacc[0][0], ah0, bl0[0], bl0[1]);                            \
        mma16816(dacc[0][1], ah0, bl0[2], bl0[3]);                            \
        mma16816(dacc[0][2], ah0, bl1[0], bl1[1]);                            \
        mma16816(dacc[0][3], ah0, bl1[2], bl1[3]);                            \
        mma16816(dacc[1][0], ah1, bl0[0], bl0[1]);                            \
        mma16816(dacc[1][1], ah1, bl0[2], bl0[3]);                            \
        mma16816(dacc[1][2], ah1, bl1[0], bl1[1]);                            \
        mma16816(dacc[1][3], ah1, bl1[2], bl1[3]);                            \
        mma16816(dacc[0][0], al0, bh0[0], bh0[1]);                            \
        mma16816(dacc[0][1], al0, bh0[2], bh0[3]);                            \
        mma16816(dacc[0][2], al0, bh1[0], bh1[1]);                            \
        mma16816(dacc[0][3], al0, bh1[2], bh1[3]);                            \
        mma16816(dacc[1][0], al1, bh0[0], bh0[1]);                            \
        mma16816(dacc[1][1], al1, bh0[2], bh0[3]);                            \
        mma16816(dacc[1][2], al1, bh1[0], bh1[1]);                            \
        mma16816(dacc[1][3], al1, bh1[2], bh1[3]);                            \
    }

    COMPUTE_HALF(0)

    // ---- split + STS half1 (disjoint bytes vs half0 readers) ----
    #pragma unroll
    for (int i = 0; i < 8; i++) {
        int lin = tid + i*256;
        int r = lin >> 4, d4 = lin & 15;
        float4 a = a1[i];
        __nv_bfloat162 h01 = __floats2bfloat162_rn(a.x, a.y);
        __nv_bfloat162 h23 = __floats2bfloat162_rn(a.z, a.w);
        __nv_bfloat162 q01 = __floats2bfloat162_rn(a.x - __bfloat162float(h01.x),
                                                   a.y - __bfloat162float(h01.y));
        __nv_bfloat162 q23 = __floats2bfloat162_rn(a.z - __bfloat162float(h23.x),
                                                   a.w - __bfloat162float(h23.y));
        uint32_t doff = r*ROWB + 128 + d4*8;
        *reinterpret_cast<uint2*>(sm + OFF_AH + doff) =
            make_uint2(*reinterpret_cast<uint32_t*>(&h01), *reinterpret_cast<uint32_t*>(&h23));
        *reinterpret_cast<uint2*>(sm + OFF_AL + doff) =
            make_uint2(*reinterpret_cast<uint32_t*>(&q01), *reinterpret_cast<uint32_t*>(&q23));
    }
    __syncthreads();

    COMPUTE_HALF(4)
#undef COMPUTE_HALF

    // ---- epilogue: direct fragment -> STG.64 ----
    float* Sout = g_S[side];
    #pragma unroll
    for (int mb = 0; mb < 2; mb++) {
        #pragma unroll
        for (int nb = 0; nb < 4; nb++) {
            int row = r0 + wm + mb*16 + (lane >> 2);
            int col = wn + nb*8 + (lane & 3)*2;
            if (row < NROW)
                *reinterpret_cast<float2*>(&Sout[(size_t)row*64 + col]) =
                    make_float2(dacc[mb][nb][0], dacc[mb][nb][1]);
            if (row + 8 < NROW)
                *reinterpret_cast<float2*>(&Sout[(size_t)(row+8)*64 + col]) =
                    make_float2(dacc[mb][nb][2], dacc[mb][nb][3]);
        }
    }
}

// ---------------- K4: gather + __expf + Z partials (both sides) ----------------
__global__ void gather_kernel(const int* __restrict__ idx, const int* __restrict__ cidx) {
    int b = blockIdx.y, bx = blockIdx.x;
    int t = threadIdx.x;
    const float* S0 = g_S[0];
    const float* S1 = g_S[1];
    float sum0 = 0.f, sum1 = 0.f;
    #pragma unroll
    for (int i = 0; i < 4; i++) {
        int k = bx*1024 + i*256 + t;
        if (k < KP1) {
            int row = (k == 0) ? idx[b] : cidx[b*KP1 + k];
            size_t off = (size_t)row * BATCH + b;
            float e0 = __expf(S0[off] * INV_T);
            float e1 = __expf(S1[off] * INV_T);
            g_e[0][b*KP1 + k] = e0;
            g_e[1][b*KP1 + k] = e1;
            sum0 += e0;
            sum1 += e1;
        }
    }
    float t0 = block_reduce_256(sum0);
    float t1 = block_reduce_256(sum1);
    if (t == 0) { g_pZ[0][b*NBX + bx] = t0; g_pZ[1][b*NBX + bx] = t1; }
}

// ---------------- K5: loss partials (polynomial log1p) ----------------
__device__ __forceinline__ float log1p_fast(float u) {
    // log1p(u) = u - u^2/2 + u^3/3 - u^4/4 (+u^5/5...); poly for u<0.1
    if (u < 0.1f)
        return u * (1.f - u * (0.5f - u * (0.33333333f - u * 0.25f)));
    return __logf(1.f + u);
}

__global__ void loss_kernel() {
    int b = blockIdx.y, bx = blockIdx.x;
    int t = threadIdx.x;

    float z0 = 0.f, z1 = 0.f;
    for (int i = t; i < NPART; i += 256) { z0 += g_pZ[0][i]; z1 += g_pZ[1][i]; }
    float zt0 = block_reduce_256(z0);
    float zt1 = block_reduce_256(z1);
    float invZ0 = 1.0f / ((zt0 / (float)NELEM) * (float)NROW);
    float invZ1 = 1.0f / ((zt1 / (float)NELEM) * (float)NROW);
    // u = (x + EPS)/MPN = e * (invZ/MPN) + EPS/MPN
    float sc0 = invZ0 * (1.0f / MPN);
    float sc1 = invZ1 * (1.0f / MPN);
    const float uoff = EPSC / MPN;

    float acc = 0.f;
    #pragma unroll
    for (int i = 0; i < 4; i++) {
        int k = bx*1024 + i*256 + t;
        if (k < KP1) {
            float e0 = g_e[0][b*KP1 + k];
            float e1 = g_e[1][b*KP1 + k];
            if (k == 0) {
                float x0 = e0 * invZ0;
                float x1 = e1 * invZ1;
                acc += log1pf(CCONST / x0) + log1pf(CCONST / x1);
            } else {
                acc += log1p_fast(e0 * sc0 + uoff) + log1p_fast(e1 * sc1 + uoff);
            }
        }
    }
    float tot = block_reduce_256(acc);
    if (t == 0) g_pL[b*NBX + bx] = tot;
}

// ---------------- K6: final scalar ----------------
__global__ void final_kernel(float* __restrict__ out) {
    int t = threadIdx.x;
    float s = 0.f;
    for (int i = t; i < NPART; i += 256) s += g_pL[i];
    float tot = block_reduce_256(s);
    if (t == 0) out[0] = tot / (float)BATCH;
}

// ---------------- launch ----------------
extern "C" void kernel_launch(void* const* d_in, const int* in_sizes, int n_in,
                              void* d_out, int out_size) {
    const float* f_s  = (const float*)d_in[0];
    const float* f_t  = (const float*)d_in[1];
    const int*   idx  = (const int*)  d_in[2];
    const int*   cidx = (const int*)  d_in[3];
    const float* Ws   = (const float*)d_in[4];
    const float* bs   = (const float*)d_in[5];
    const float* Wt   = (const float*)d_in[6];
    const float* bt   = (const float*)d_in[7];
    const float* mem1 = (const float*)d_in[8];
    const float* mem2 = (const float*)d_in[9];

    cudaFuncSetAttribute(gemm_mma, cudaFuncAttributeMaxDynamicSharedMemorySize, SMEM_DYN);

    embed_kernel <<<dim3(16, 2),       256>>>(f_s, f_t, Ws, Wt);
    norm_kernel  <<<dim3(BATCH, 2),    128>>>(bs, bt);
    prep_kernel  <<<1, 32>>>();
    gemm_mma     <<<dim3(782, 2),      256, SMEM_DYN>>>(mem1, mem2);
    gather_kernel<<<dim3(NBX, BATCH),  256>>>(idx, cidx);
    loss_kernel  <<<dim3(NBX, BATCH),  256>>>();
    final_kernel <<<1,                 256>>>((float*)d_out);
}